// round 15
// baseline (speedup 1.0000x reference)
#include <cuda_runtime.h>
#include <cuda_bf16.h>
#include <cstdint>
#include <math.h>

// ---------------- problem constants ----------------
// B=64, T=256, DIN=128, H=256, DZ=8, DX=8
#define ROWS_ 16384              // B*T
#define MZ_OFF 0
#define CHOL_OFF 131072          // 16384*8
#define MX_OFF  33685504         // CHOL_OFF + 8*64*256*256
#define CV_OFF  33816576         // MX_OFF + 16384*8

// ---------------- device scratch (no allocation allowed) ----------------
__device__ __align__(16) float  g_xproj[ROWS_ * 768];   // 50 MB
__device__ __align__(16) float  g_enc[ROWS_ * 256];     // 16 MB
__device__ __align__(16) float  g_op[ROWS_ * 96];       // 6.3 MB
__device__ __align__(16) float  g_wihT[128 * 768];      // W_ih^T  [K=128, N=768]
__device__ __align__(16) float  g_wcatT[256 * 96];      // packed head weights [K=256, N=96]
__device__ __align__(16) float  g_bcat[96];

// ---------------- f32x2 helpers ----------------
__device__ __forceinline__ void fma2(unsigned long long& d, unsigned long long a, unsigned long long b) {
    asm("fma.rn.f32x2 %0, %1, %2, %0;" : "+l"(d) : "l"(a), "l"(b));
}
__device__ __forceinline__ unsigned long long dup2(float a) {
    unsigned long long r; asm("mov.b64 %0, {%1, %1};" : "=l"(r) : "f"(a)); return r;
}
__device__ __forceinline__ float2 unpack2(unsigned long long v) {
    float2 r; asm("mov.b64 {%0, %1}, %2;" : "=f"(r.x), "=f"(r.y) : "l"(v)); return r;
}
__device__ __forceinline__ unsigned long long add2(unsigned long long a, unsigned long long b) {
    unsigned long long r; asm("add.rn.f32x2 %0, %1, %2;" : "=l"(r) : "l"(a), "l"(b)); return r;
}
__device__ __forceinline__ unsigned long long pack2(float lo, float hi) {
    unsigned long long r; asm("mov.b64 %0, {%1, %2};" : "=l"(r) : "f"(lo), "f"(hi)); return r;
}
__device__ __forceinline__ uint32_t smem_u32(const void* p) {
    uint32_t a; asm("{ .reg .u64 t; cvta.to.shared.u64 t, %1; cvt.u32.u64 %0, t; }" : "=r"(a) : "l"(p));
    return a;
}
__device__ __forceinline__ void st_cluster_b64(uint32_t addr, uint32_t rank, unsigned long long v) {
    uint32_t ra;
    asm volatile("mapa.shared::cluster.u32 %0, %1, %2;" : "=r"(ra) : "r"(addr), "r"(rank));
    asm volatile("st.shared::cluster.b64 [%0], %1;" :: "r"(ra), "l"(v) : "memory");
}

// ---------------- prep: transposes + packing ----------------
__global__ void __launch_bounds__(256) prep_kernel(
    const float* __restrict__ Wih,
    const float* __restrict__ Wmz, const float* __restrict__ Wmx,
    const float* __restrict__ Wpz, const float* __restrict__ Wcx,
    const float* __restrict__ bmz, const float* __restrict__ bmx,
    const float* __restrict__ bpz, const float* __restrict__ bcx)
{
    int i = blockIdx.x * 256 + threadIdx.x;
    if (i < 128 * 768) {                       // W_ih^T
        int k = i / 768, n = i % 768;
        g_wihT[i] = Wih[n * 128 + k];
        return;
    }
    int i3 = i - 128 * 768;
    if (i3 < 24576) {                          // packed head weights^T
        int k = i3 / 96, c = i3 % 96;
        float v;
        if (c < 8)       v = Wmz[c * 256 + k];
        else if (c < 16) v = Wmx[(c - 8) * 256 + k];
        else if (c < 32) v = Wpz[(c - 16) * 256 + k];
        else             v = Wcx[(c - 32) * 256 + k];
        g_wcatT[i3] = v;
        return;
    }
    int i4 = i3 - 24576;
    if (i4 < 96) {
        float v;
        if (i4 < 8)       v = bmz[i4];
        else if (i4 < 16) v = bmx[i4 - 8];
        else if (i4 < 32) v = bpz[i4 - 16];
        else              v = bcx[i4 - 32];
        g_bcat[i4] = v;
    }
}

// ---------------- GEMM: C[M,N] = A[M,K] @ B[K,N] + bias (row-major) ----------------
template <int BM, int BN, int BK, int TM, int TN>
__global__ void __launch_bounds__(256) gemm_kernel(
    const float* __restrict__ A, const float* __restrict__ B,
    const float* __restrict__ bias, float* __restrict__ C,
    int M, int N, int K)
{
    constexpr int TX = BN / TN;
    constexpr int NH = TN / 2;
    __shared__ float Asm[BK][BM];
    __shared__ float Bsm[BK][BN];

    int tid = threadIdx.x;
    int tx = tid % TX, ty = tid / TX;
    int m0 = blockIdx.y * BM, n0 = blockIdx.x * BN;

    unsigned long long acc[TM][NH];
#pragma unroll
    for (int m = 0; m < TM; m++)
#pragma unroll
        for (int i = 0; i < NH; i++) acc[m][i] = 0ull;

    for (int k0 = 0; k0 < K; k0 += BK) {
        for (int i = tid; i < BM * BK / 4; i += 256) {
            int r = i / (BK / 4), c = i % (BK / 4);
            float4 v = *(const float4*)(A + (size_t)(m0 + r) * K + k0 + c * 4);
            Asm[c * 4 + 0][r] = v.x; Asm[c * 4 + 1][r] = v.y;
            Asm[c * 4 + 2][r] = v.z; Asm[c * 4 + 3][r] = v.w;
        }
        for (int i = tid; i < BK * BN / 4; i += 256) {
            int r = i / (BN / 4), c = i % (BN / 4);
            *(float4*)&Bsm[r][c * 4] = *(const float4*)(B + (size_t)(k0 + r) * N + n0 + c * 4);
        }
        __syncthreads();
#pragma unroll
        for (int k = 0; k < BK; k++) {
            float4 av = *(const float4*)&Asm[k][ty * TM];
            unsigned long long am[TM];
            am[0] = dup2(av.x); am[1] = dup2(av.y); am[2] = dup2(av.z); am[3] = dup2(av.w);
            const unsigned long long* bp = (const unsigned long long*)&Bsm[k][tx * TN];
            unsigned long long bv[NH];
#pragma unroll
            for (int i = 0; i < NH; i++) bv[i] = bp[i];
#pragma unroll
            for (int m = 0; m < TM; m++)
#pragma unroll
                for (int i = 0; i < NH; i++) fma2(acc[m][i], am[m], bv[i]);
        }
        __syncthreads();
    }

#pragma unroll
    for (int m = 0; m < TM; m++) {
        int row = m0 + ty * TM + m;
#pragma unroll
        for (int i = 0; i < NH; i++) {
            float2 s = unpack2(acc[m][i]);
            int col = n0 + tx * TN + i * 2;
            C[(size_t)row * N + col]     = s.x + bias[col];
            C[(size_t)row * N + col + 1] = s.y + bias[col + 1];
        }
    }
}

// ---------------- cluster GRU (8-CTA clusters, 4 batches/cluster) ----------------
// 16 clusters x 8 CTAs, 192 threads/CTA. Cluster ci handles batches 4ci..4ci+3.
// CTA rank r owns j-slice [32r, 32r+32): 3 gates x 32 j x 256 k fp32 = 96 KB SMEM.
// Thread (khalf = tid/96, g = (tid%96)/32, jl = tid%32): k-range [128*khalf, +128).
// Weight rows padded 256->260 floats: LDS.128 conflict-free (4-bank offset/jl).
// h stored as float4 quads (b0,b1,b2,b3) per unit j: hq[2][256], double-buffered.
// gacc[khalf][g*32+jl][pair] partial dot results (ull), one STS.128 per thread.
#define GRU_ROW    260
#define GRU_W_FLOATS (96 * GRU_ROW)                       // 24960
#define GRU_HQ_FLOATS (2 * 256 * 4)                       // 2048
#define GRU_SMEM_BYTES (GRU_W_FLOATS*4 + GRU_HQ_FLOATS*4 + 2*96*2*8)  // 111104

__global__ void __cluster_dims__(8, 1, 1) __launch_bounds__(192)
gru_cluster_kernel(const float* __restrict__ Whh, const float* __restrict__ bhh,
                   const float* __restrict__ xproj, float* __restrict__ enc)
{
    extern __shared__ float smem[];
    float* sW = smem;                                     // [96][260]
    float4* hq = (float4*)(smem + GRU_W_FLOATS);          // [2][256]
    unsigned long long* gacc =
        (unsigned long long*)(smem + GRU_W_FLOATS + GRU_HQ_FLOATS); // [2][96][2]

    int tid = threadIdx.x;
    uint32_t rank;
    asm("mov.u32 %0, %%cluster_ctarank;" : "=r"(rank));
    int jbase = (int)rank * 32;
    int b0 = (blockIdx.x >> 3) * 4;

    // load weights: sW[(g*32+jl)*260 + k] = Whh[(g*256 + jbase + jl)*256 + k]
    for (int idx = tid; idx < 96 * 256; idx += 192) {
        int row = idx >> 8;               // g*32 + jl
        int k = idx & 255;
        int g = row >> 5, jl = row & 31;
        sW[row * GRU_ROW + k] = Whh[(g * 256 + jbase + jl) * 256 + k];
    }
    // init h quads = 0 (both buffers)
    for (int i = tid; i < 512; i += 192) hq[i] = make_float4(0.f, 0.f, 0.f, 0.f);

    // dot-phase role
    int khalf = tid / 96;                 // warp-uniform (warps 0-2: 0, 3-5: 1)
    int g = (tid % 96) >> 5;              // warp-uniform gate
    int jl = tid & 31;
    // combine-phase role (tid < 32): global j
    int jg = jbase + tid;
    float br = 0.f, bz = 0.f, bn = 0.f;
    if (tid < 32) { br = bhh[jg]; bz = bhh[256 + jg]; bn = bhh[512 + jg]; }

    uint32_t hq_addr = smem_u32(hq);
    const float4* wrow4 = (const float4*)(sW + ((g * 32 + jl) * GRU_ROW) + khalf * 128);
    unsigned long long* gslot = gacc + ((khalf * 96) + (g * 32 + jl)) * 2;

    __syncthreads();
    asm volatile("barrier.cluster.arrive.aligned;" ::: "memory");
    asm volatile("barrier.cluster.wait.aligned;" ::: "memory");

    int cur = 0;
    for (int t = 0; t < 256; t++) {
        // prefetch xproj for combine (tid < 32); latency hides under dot
        float xr[4], xz[4], xn[4];
        if (tid < 32) {
#pragma unroll
            for (int bi = 0; bi < 4; bi++) {
                const float* xp = xproj + ((size_t)(b0 + bi) * 256 + t) * 768;
                xr[bi] = xp[jg]; xz[bi] = xp[256 + jg]; xn[bi] = xp[512 + jg];
            }
        }

        // dot phase: thread computes partial sum over its 128 k's for 4 batches
        {
            const float4* hp = hq + cur * 256 + khalf * 128;
            unsigned long long aA0 = 0ull, aA1 = 0ull, aB0 = 0ull, aB1 = 0ull;
#pragma unroll 8
            for (int i = 0; i < 32; i++) {                // 4 k's per iter
                float4 w = wrow4[i];                       // LDS.128, conflict-free
                float4 h0 = hp[4 * i];                     // broadcast quads
                float4 h1 = hp[4 * i + 1];
                float4 h2 = hp[4 * i + 2];
                float4 h3 = hp[4 * i + 3];
                unsigned long long d0 = dup2(w.x), d1 = dup2(w.y);
                unsigned long long d2 = dup2(w.z), d3 = dup2(w.w);
                fma2(aA0, d0, *(unsigned long long*)&h0.x);
                fma2(aB0, d0, *(unsigned long long*)&h0.z);
                fma2(aA1, d1, *(unsigned long long*)&h1.x);
                fma2(aB1, d1, *(unsigned long long*)&h1.z);
                fma2(aA0, d2, *(unsigned long long*)&h2.x);
                fma2(aB0, d2, *(unsigned long long*)&h2.z);
                fma2(aA1, d3, *(unsigned long long*)&h3.x);
                fma2(aB1, d3, *(unsigned long long*)&h3.z);
            }
            unsigned long long pA = add2(aA0, aA1);
            unsigned long long pB = add2(aB0, aB1);
            asm volatile("st.shared.v2.u64 [%0], {%1, %2};"
                         :: "r"(smem_u32(gslot)), "l"(pA), "l"(pB) : "memory");
        }
        __syncthreads();

        // combine phase (tid < 32): unit jg, 4 batches
        if (tid < 32) {
            float hrv[4], hzv[4], hnv[4];
#pragma unroll
            for (int gg = 0; gg < 3; gg++) {
                const unsigned long long* s0 = gacc + (gg * 32 + tid) * 2;          // khalf 0
                const unsigned long long* s1 = gacc + (96 + gg * 32 + tid) * 2;     // khalf 1
                float2 pa = unpack2(add2(s0[0], s1[0]));
                float2 pb = unpack2(add2(s0[1], s1[1]));
                float* dstp = (gg == 0) ? hrv : (gg == 1) ? hzv : hnv;
                dstp[0] = pa.x; dstp[1] = pa.y; dstp[2] = pb.x; dstp[3] = pb.y;
            }
            float4 hprev = hq[cur * 256 + jg];
            float hpv[4] = {hprev.x, hprev.y, hprev.z, hprev.w};
            float hnew[4];
#pragma unroll
            for (int bi = 0; bi < 4; bi++) {
                float r = 1.f / (1.f + __expf(-(xr[bi] + hrv[bi] + br)));
                float z = 1.f / (1.f + __expf(-(xz[bi] + hzv[bi] + bz)));
                float n = tanhf(xn[bi] + r * (hnv[bi] + bn));
                hnew[bi] = (1.f - z) * n + z * hpv[bi];
            }

            // broadcast new h quad to all 8 CTAs' next buffer
            unsigned long long lo = pack2(hnew[0], hnew[1]);
            unsigned long long hi = pack2(hnew[2], hnew[3]);
            uint32_t dst = hq_addr + ((cur ^ 1) * 256 + jg) * 16;
#pragma unroll
            for (uint32_t rr = 0; rr < 8; rr++) {
                st_cluster_b64(dst, rr, lo);
                st_cluster_b64(dst + 8, rr, hi);
            }
#pragma unroll
            for (int bi = 0; bi < 4; bi++)
                enc[((size_t)(b0 + bi) * 256 + t) * 256 + jg] = hnew[bi];
        }

        // one cluster barrier per step: orders peer h-writes (release/acquire)
        asm volatile("barrier.cluster.arrive.aligned;" ::: "memory");
        asm volatile("barrier.cluster.wait.aligned;" ::: "memory");
        cur ^= 1;
    }
}

// ---------------- small outputs: mean_z, mean_x (anchored), cov_x ----------------
__global__ void __launch_bounds__(512) heads_out_kernel(
    const float* __restrict__ op, float* __restrict__ out)
{
    int idx = blockIdx.x * 512 + threadIdx.x;   // 1,310,720 total
    if (idx < 131072) {                          // mean_z
        int row = idx >> 3, c = idx & 7;
        out[MZ_OFF + idx] = op[row * 96 + c];
    } else if (idx < 262144) {                   // mean_x with t=0 anchoring of dims 0,1
        int i = idx - 131072;
        int row = i >> 3, c = i & 7;
        float v = op[row * 96 + 8 + c];
        if (c < 2) v -= op[((row >> 8) << 8) * 96 + 8 + c];
        out[MX_OFF + i] = v;
    } else {                                     // cov_x
        int i = idx - 262144;
        if (i < 1048576) {
            int row = i >> 6, c = i & 63;
            out[CV_OFF + i] = op[row * 96 + 32 + c];
        }
    }
}

// ---------------- chol_z: [DZ,B,T,T] banded fill ----------------
__global__ void __launch_bounds__(512) chol_kernel(
    const float* __restrict__ op, float* __restrict__ out)
{
    int q = blockIdx.x * 512 + threadIdx.x;      // 8,388,608 float4s
    int j4 = q & 63;
    int rowid = q >> 6;                          // d*16384 + b*256 + i
    int i = rowid & 255;
    int b = (rowid >> 8) & 63;
    int d = rowid >> 14;

    float vv0 = 0.f, vv1 = 0.f, vv2 = 0.f, vv3 = 0.f;
    int jb = j4 << 2;
    int oprow = (b << 8) + i;
    if (i >= jb && i < jb + 4) {                 // diagonal: softplus
        float x = op[oprow * 96 + 16 + d];
        float sp = (x > 15.f) ? x : log1pf(expf(x));
        int p = i - jb;
        if (p == 0) vv0 = sp; else if (p == 1) vv1 = sp; else if (p == 2) vv2 = sp; else vv3 = sp;
    }
    int ip = i + 1;
    if (i < 255 && ip >= jb && ip < jb + 4) {    // superdiagonal
        float offv = op[oprow * 96 + 24 + d];
        int p = ip - jb;
        if (p == 0) vv0 = offv; else if (p == 1) vv1 = offv; else if (p == 2) vv2 = offv; else vv3 = offv;
    }
    *(float4*)(out + CHOL_OFF + ((size_t)q << 2)) = make_float4(vv0, vv1, vv2, vv3);
}

// ---------------- launch ----------------
extern "C" void kernel_launch(void* const* d_in, const int* in_sizes, int n_in,
                              void* d_out, int out_size)
{
    const float* y    = (const float*)d_in[0];
    const float* Wih  = (const float*)d_in[1];
    const float* Whh  = (const float*)d_in[2];
    const float* bih  = (const float*)d_in[3];
    const float* bhh  = (const float*)d_in[4];
    const float* Wmz  = (const float*)d_in[5];
    const float* bmz  = (const float*)d_in[6];
    const float* Wmx  = (const float*)d_in[7];
    const float* bmx  = (const float*)d_in[8];
    const float* Wpz  = (const float*)d_in[9];
    const float* bpz  = (const float*)d_in[10];
    const float* Wcx  = (const float*)d_in[11];
    const float* bcx  = (const float*)d_in[12];
    float* out = (float*)d_out;

    float *xproj, *enc, *op, *wihT, *wcatT, *bcat;
    cudaGetSymbolAddress((void**)&xproj, g_xproj);
    cudaGetSymbolAddress((void**)&enc,   g_enc);
    cudaGetSymbolAddress((void**)&op,    g_op);
    cudaGetSymbolAddress((void**)&wihT,  g_wihT);
    cudaGetSymbolAddress((void**)&wcatT, g_wcatT);
    cudaGetSymbolAddress((void**)&bcat,  g_bcat);

    cudaFuncSetAttribute(gru_cluster_kernel,
                         cudaFuncAttributeMaxDynamicSharedMemorySize, GRU_SMEM_BYTES);

    prep_kernel<<<737, 256>>>(Wih, Wmz, Wmx, Wpz, Wcx, bmz, bmx, bpz, bcx);

    // x_proj = y @ W_ih^T + b_ih : [16384,768]
    gemm_kernel<64, 64, 32, 4, 4><<<dim3(12, 256), 256>>>(y, wihT, bih, xproj, 16384, 768, 128);

    // GRU recurrence -> enc [16384,256]
    gru_cluster_kernel<<<128, 192, GRU_SMEM_BYTES>>>(Whh, bhh, xproj, enc);

    // all heads fused: [16384,96] = enc @ Wcat^T + bcat
    gemm_kernel<64, 96, 32, 4, 6><<<dim3(1, 256), 256>>>(enc, wcatT, bcat, op, 16384, 96, 256);

    heads_out_kernel<<<2560, 512>>>(op, out);
    chol_kernel<<<16384, 512>>>(op, out);
}

// round 16
// speedup vs baseline: 1.4569x; 1.4569x over previous
#include <cuda_runtime.h>
#include <cuda_bf16.h>
#include <cstdint>
#include <math.h>

// ---------------- problem constants ----------------
// B=64, T=256, DIN=128, H=256, DZ=8, DX=8
#define ROWS_ 16384              // B*T
#define MZ_OFF 0
#define CHOL_OFF 131072          // 16384*8
#define MX_OFF  33685504         // CHOL_OFF + 8*64*256*256
#define CV_OFF  33816576         // MX_OFF + 16384*8

// ---------------- device scratch (no allocation allowed) ----------------
__device__ __align__(16) float  g_xproj[ROWS_ * 768];   // 50 MB
__device__ __align__(16) float  g_enc[ROWS_ * 256];     // 16 MB
__device__ __align__(16) float  g_op[ROWS_ * 96];       // 6.3 MB
__device__ __align__(16) float  g_wihT[128 * 768];      // W_ih^T  [K=128, N=768]
__device__ __align__(16) float  g_wcatT[256 * 96];      // packed head weights [K=256, N=96]
__device__ __align__(16) float  g_bcat[96];

// ---------------- f32x2 helpers ----------------
__device__ __forceinline__ void fma2(unsigned long long& d, unsigned long long a, unsigned long long b) {
    asm("fma.rn.f32x2 %0, %1, %2, %0;" : "+l"(d) : "l"(a), "l"(b));
}
__device__ __forceinline__ unsigned long long dup2(float a) {
    unsigned long long r; asm("mov.b64 %0, {%1, %1};" : "=l"(r) : "f"(a)); return r;
}
__device__ __forceinline__ float2 unpack2(unsigned long long v) {
    float2 r; asm("mov.b64 {%0, %1}, %2;" : "=f"(r.x), "=f"(r.y) : "l"(v)); return r;
}
__device__ __forceinline__ unsigned long long add2(unsigned long long a, unsigned long long b) {
    unsigned long long r; asm("add.rn.f32x2 %0, %1, %2;" : "=l"(r) : "l"(a), "l"(b)); return r;
}
__device__ __forceinline__ uint32_t smem_u32(const void* p) {
    uint32_t a; asm("{ .reg .u64 t; cvta.to.shared.u64 t, %1; cvt.u32.u64 %0, t; }" : "=r"(a) : "l"(p));
    return a;
}
__device__ __forceinline__ uint32_t ctarank() {
    uint32_t r; asm("mov.u32 %0, %%cluster_ctarank;" : "=r"(r)); return r;
}
__device__ __forceinline__ void st_cluster_b64(uint32_t addr, uint32_t rank, unsigned long long v) {
    uint32_t ra;
    asm volatile("mapa.shared::cluster.u32 %0, %1, %2;" : "=r"(ra) : "r"(addr), "r"(rank));
    asm volatile("st.shared::cluster.b64 [%0], %1;" :: "r"(ra), "l"(v) : "memory");
}

// ---------------- prep: transposes + packing ----------------
__global__ void __launch_bounds__(256) prep_kernel(
    const float* __restrict__ Wih,
    const float* __restrict__ Wmz, const float* __restrict__ Wmx,
    const float* __restrict__ Wpz, const float* __restrict__ Wcx,
    const float* __restrict__ bmz, const float* __restrict__ bmx,
    const float* __restrict__ bpz, const float* __restrict__ bcx)
{
    int i = blockIdx.x * 256 + threadIdx.x;
    if (i < 128 * 768) {                       // W_ih^T
        int k = i / 768, n = i % 768;
        g_wihT[i] = Wih[n * 128 + k];
        return;
    }
    int i3 = i - 128 * 768;
    if (i3 < 24576) {                          // packed head weights^T
        int k = i3 / 96, c = i3 % 96;
        float v;
        if (c < 8)       v = Wmz[c * 256 + k];
        else if (c < 16) v = Wmx[(c - 8) * 256 + k];
        else if (c < 32) v = Wpz[(c - 16) * 256 + k];
        else             v = Wcx[(c - 32) * 256 + k];
        g_wcatT[i3] = v;
        return;
    }
    int i4 = i3 - 24576;
    if (i4 < 96) {
        float v;
        if (i4 < 8)       v = bmz[i4];
        else if (i4 < 16) v = bmx[i4 - 8];
        else if (i4 < 32) v = bpz[i4 - 16];
        else              v = bcx[i4 - 32];
        g_bcat[i4] = v;
    }
}

// ---------------- GEMM: C[M,N] = A[M,K] @ B[K,N] + bias (row-major) ----------------
template <int BM, int BN, int BK, int TM, int TN>
__global__ void __launch_bounds__(256) gemm_kernel(
    const float* __restrict__ A, const float* __restrict__ B,
    const float* __restrict__ bias, float* __restrict__ C,
    int M, int N, int K)
{
    constexpr int TX = BN / TN;
    constexpr int NH = TN / 2;
    __shared__ float Asm[BK][BM];
    __shared__ float Bsm[BK][BN];

    int tid = threadIdx.x;
    int tx = tid % TX, ty = tid / TX;
    int m0 = blockIdx.y * BM, n0 = blockIdx.x * BN;

    unsigned long long acc[TM][NH];
#pragma unroll
    for (int m = 0; m < TM; m++)
#pragma unroll
        for (int i = 0; i < NH; i++) acc[m][i] = 0ull;

    for (int k0 = 0; k0 < K; k0 += BK) {
        for (int i = tid; i < BM * BK / 4; i += 256) {
            int r = i / (BK / 4), c = i % (BK / 4);
            float4 v = *(const float4*)(A + (size_t)(m0 + r) * K + k0 + c * 4);
            Asm[c * 4 + 0][r] = v.x; Asm[c * 4 + 1][r] = v.y;
            Asm[c * 4 + 2][r] = v.z; Asm[c * 4 + 3][r] = v.w;
        }
        for (int i = tid; i < BK * BN / 4; i += 256) {
            int r = i / (BN / 4), c = i % (BN / 4);
            *(float4*)&Bsm[r][c * 4] = *(const float4*)(B + (size_t)(k0 + r) * N + n0 + c * 4);
        }
        __syncthreads();
#pragma unroll
        for (int k = 0; k < BK; k++) {
            float4 av = *(const float4*)&Asm[k][ty * TM];
            unsigned long long am[TM];
            am[0] = dup2(av.x); am[1] = dup2(av.y); am[2] = dup2(av.z); am[3] = dup2(av.w);
            const unsigned long long* bp = (const unsigned long long*)&Bsm[k][tx * TN];
            unsigned long long bv[NH];
#pragma unroll
            for (int i = 0; i < NH; i++) bv[i] = bp[i];
#pragma unroll
            for (int m = 0; m < TM; m++)
#pragma unroll
                for (int i = 0; i < NH; i++) fma2(acc[m][i], am[m], bv[i]);
        }
        __syncthreads();
    }

#pragma unroll
    for (int m = 0; m < TM; m++) {
        int row = m0 + ty * TM + m;
#pragma unroll
        for (int i = 0; i < NH; i++) {
            float2 s = unpack2(acc[m][i]);
            int col = n0 + tx * TN + i * 2;
            C[(size_t)row * N + col]     = s.x + bias[col];
            C[(size_t)row * N + col + 1] = s.y + bias[col + 1];
        }
    }
}

// ---------------- cluster GRU (4-CTA clusters, 2 batches, 384 threads k-split) ----------------
// 32 clusters x 4 CTAs, 384 threads/CTA. Cluster c handles batches (2c, 2c+1).
// CTA rank r owns j-slice [64r, 64r+64): weights SMEM-resident, rows padded
// 256->260 floats (LDS.128 conflict-free: 4-bank offset per jl).
// Thread role: khalf = tid/192 (k in [128*khalf,+128)), g = (tid%192)/64, jl = tid%64.
// 12 warps/SM for latency hiding; k-partials reduced through gacc.
// hbuf: [2][512] floats = pairs (b0,b1) per global j, double buffered.
// gacc: ull[2][192] partial dot results.
#define GRU_ROW    260
#define GRU_W_FLOATS (3*64*GRU_ROW)                     // 49920
#define GRU_SMEM_BYTES (GRU_W_FLOATS*4 + 2*512*4 + 2*192*8) // 206848

__global__ void __cluster_dims__(4, 1, 1) __launch_bounds__(384)
gru_cluster_kernel(const float* __restrict__ Whh, const float* __restrict__ bhh,
                   const float* __restrict__ xproj, float* __restrict__ enc)
{
    extern __shared__ float smem[];
    float* sW = smem;                                   // [3*64][260]
    float* hbuf = smem + GRU_W_FLOATS;                  // [2][512]
    unsigned long long* gacc = (unsigned long long*)(hbuf + 1024); // [2][192]

    int tid = threadIdx.x;
    uint32_t rank = ctarank();
    int jbase = (int)rank * 64;
    int b0 = (blockIdx.x >> 2) * 2;

    // load weights: sW[(g*64+jl)*260 + k] = Whh[(g*256 + jbase + jl)*256 + k]
    for (int idx = tid; idx < 3 * 64 * 256; idx += 384) {
        int g = idx >> 14;             // 16384 per gate
        int rem = idx & 16383;
        int jl = rem >> 8, k = rem & 255;
        sW[(g * 64 + jl) * GRU_ROW + k] = Whh[(g * 256 + jbase + jl) * 256 + k];
    }
    // init h = 0 (both buffers)
    for (int i = tid; i < 1024; i += 384) hbuf[i] = 0.f;

    // dot-phase role
    int khalf = tid / 192;             // warp-uniform (6 warps each)
    int g = (tid % 192) >> 6;          // warp-uniform gate (2 warps each)
    int jl = tid & 63;
    // combine-phase role (tid < 64): global j
    int jg = jbase + tid;
    float br = 0.f, bz = 0.f, bn = 0.f;
    if (tid < 64) { br = bhh[jg]; bz = bhh[256 + jg]; bn = bhh[512 + jg]; }

    uint32_t hbuf_addr = smem_u32(hbuf);
    const float4* wrow4 = (const float4*)(sW + (g * 64 + jl) * GRU_ROW + khalf * 128);
    unsigned long long* gslot = gacc + khalf * 192 + g * 64 + jl;

    __syncthreads();
    asm volatile("barrier.cluster.arrive.aligned;" ::: "memory");
    asm volatile("barrier.cluster.wait.aligned;" ::: "memory");

    const float* xpb0 = xproj + (size_t)b0 * 256 * 768;
    const float* xpb1 = xpb0 + (size_t)256 * 768;

    int cur = 0;
    for (int t = 0; t < 256; t++) {
        // prefetch xproj for combine (tid < 64); latency hides under dot
        float xr0, xz0, xn0, xr1, xz1, xn1;
        if (tid < 64) {
            const float* xp0 = xpb0 + (size_t)t * 768;
            const float* xp1 = xpb1 + (size_t)t * 768;
            xr0 = xp0[jg]; xz0 = xp0[256 + jg]; xn0 = xp0[512 + jg];
            xr1 = xp1[jg]; xz1 = xp1[256 + jg]; xn1 = xp1[512 + jg];
        }

        // dot phase: partial sum over this thread's 128 k's (both batches)
        {
            const float4* hp4 = (const float4*)(hbuf + cur * 512) + khalf * 64;
            unsigned long long a0 = 0ull, a1 = 0ull, a2 = 0ull, a3 = 0ull;
#pragma unroll 8
            for (int i = 0; i < 32; i++) {                 // 4 k's per iter
                float4 w = wrow4[i];                        // LDS.128, conflict-free
                float4 hA = hp4[2 * i];                     // pair-quads (broadcast)
                float4 hB = hp4[2 * i + 1];
                fma2(a0, dup2(w.x), *(unsigned long long*)&hA.x);
                fma2(a1, dup2(w.y), *(unsigned long long*)&hA.z);
                fma2(a2, dup2(w.z), *(unsigned long long*)&hB.x);
                fma2(a3, dup2(w.w), *(unsigned long long*)&hB.z);
            }
            *gslot = add2(add2(a0, a2), add2(a1, a3));
        }
        __syncthreads();

        // combine phase (tid < 64)
        if (tid < 64) {
            float2 sr = unpack2(add2(gacc[tid],       gacc[192 + tid]));
            float2 sz = unpack2(add2(gacc[64 + tid],  gacc[256 + tid]));
            float2 sn = unpack2(add2(gacc[128 + tid], gacc[320 + tid]));
            float hr0 = sr.x + br, hr1 = sr.y + br;
            float hz0 = sz.x + bz, hz1 = sz.y + bz;
            float hn0 = sn.x + bn, hn1 = sn.y + bn;

            float r0 = 1.f / (1.f + __expf(-(xr0 + hr0)));
            float z0 = 1.f / (1.f + __expf(-(xz0 + hz0)));
            float n0 = tanhf(xn0 + r0 * hn0);
            float r1 = 1.f / (1.f + __expf(-(xr1 + hr1)));
            float z1 = 1.f / (1.f + __expf(-(xz1 + hz1)));
            float n1 = tanhf(xn1 + r1 * hn1);

            // previous h for THIS global unit jg
            float hp0 = hbuf[cur * 512 + 2 * jg];
            float hp1 = hbuf[cur * 512 + 2 * jg + 1];
            float h0 = (1.f - z0) * n0 + z0 * hp0;
            float h1 = (1.f - z1) * n1 + z1 * hp1;

            // broadcast new h pair to all 4 CTAs' next buffer
            float2 hv = make_float2(h0, h1);
            unsigned long long hvq = *(unsigned long long*)&hv;
            uint32_t dst = hbuf_addr + (((cur ^ 1) * 512 + 2 * jg) << 2);
            st_cluster_b64(dst, 0, hvq);
            st_cluster_b64(dst, 1, hvq);
            st_cluster_b64(dst, 2, hvq);
            st_cluster_b64(dst, 3, hvq);

            enc[((size_t)b0 * 256 + t) * 256 + jg] = h0;
            enc[((size_t)(b0 + 1) * 256 + t) * 256 + jg] = h1;
        }

        // one cluster barrier per step: orders peer h-writes (release/acquire)
        asm volatile("barrier.cluster.arrive.aligned;" ::: "memory");
        asm volatile("barrier.cluster.wait.aligned;" ::: "memory");
        cur ^= 1;
    }
}

// ---------------- small outputs: mean_z, mean_x (anchored), cov_x ----------------
__global__ void __launch_bounds__(512) heads_out_kernel(
    const float* __restrict__ op, float* __restrict__ out)
{
    int idx = blockIdx.x * 512 + threadIdx.x;   // 1,310,720 total
    if (idx < 131072) {                          // mean_z
        int row = idx >> 3, c = idx & 7;
        out[MZ_OFF + idx] = op[row * 96 + c];
    } else if (idx < 262144) {                   // mean_x with t=0 anchoring of dims 0,1
        int i = idx - 131072;
        int row = i >> 3, c = i & 7;
        float v = op[row * 96 + 8 + c];
        if (c < 2) v -= op[((row >> 8) << 8) * 96 + 8 + c];
        out[MX_OFF + i] = v;
    } else {                                     // cov_x
        int i = idx - 262144;
        if (i < 1048576) {
            int row = i >> 6, c = i & 63;
            out[CV_OFF + i] = op[row * 96 + 32 + c];
        }
    }
}

// ---------------- chol_z: [DZ,B,T,T] banded fill ----------------
__global__ void __launch_bounds__(512) chol_kernel(
    const float* __restrict__ op, float* __restrict__ out)
{
    int q = blockIdx.x * 512 + threadIdx.x;      // 8,388,608 float4s
    int j4 = q & 63;
    int rowid = q >> 6;                          // d*16384 + b*256 + i
    int i = rowid & 255;
    int b = (rowid >> 8) & 63;
    int d = rowid >> 14;

    float vv0 = 0.f, vv1 = 0.f, vv2 = 0.f, vv3 = 0.f;
    int jb = j4 << 2;
    int oprow = (b << 8) + i;
    if (i >= jb && i < jb + 4) {                 // diagonal: softplus
        float x = op[oprow * 96 + 16 + d];
        float sp = (x > 15.f) ? x : log1pf(expf(x));
        int p = i - jb;
        if (p == 0) vv0 = sp; else if (p == 1) vv1 = sp; else if (p == 2) vv2 = sp; else vv3 = sp;
    }
    int ip = i + 1;
    if (i < 255 && ip >= jb && ip < jb + 4) {    // superdiagonal
        float offv = op[oprow * 96 + 24 + d];
        int p = ip - jb;
        if (p == 0) vv0 = offv; else if (p == 1) vv1 = offv; else if (p == 2) vv2 = offv; else vv3 = offv;
    }
    *(float4*)(out + CHOL_OFF + ((size_t)q << 2)) = make_float4(vv0, vv1, vv2, vv3);
}

// ---------------- launch ----------------
extern "C" void kernel_launch(void* const* d_in, const int* in_sizes, int n_in,
                              void* d_out, int out_size)
{
    const float* y    = (const float*)d_in[0];
    const float* Wih  = (const float*)d_in[1];
    const float* Whh  = (const float*)d_in[2];
    const float* bih  = (const float*)d_in[3];
    const float* bhh  = (const float*)d_in[4];
    const float* Wmz  = (const float*)d_in[5];
    const float* bmz  = (const float*)d_in[6];
    const float* Wmx  = (const float*)d_in[7];
    const float* bmx  = (const float*)d_in[8];
    const float* Wpz  = (const float*)d_in[9];
    const float* bpz  = (const float*)d_in[10];
    const float* Wcx  = (const float*)d_in[11];
    const float* bcx  = (const float*)d_in[12];
    float* out = (float*)d_out;

    float *xproj, *enc, *op, *wihT, *wcatT, *bcat;
    cudaGetSymbolAddress((void**)&xproj, g_xproj);
    cudaGetSymbolAddress((void**)&enc,   g_enc);
    cudaGetSymbolAddress((void**)&op,    g_op);
    cudaGetSymbolAddress((void**)&wihT,  g_wihT);
    cudaGetSymbolAddress((void**)&wcatT, g_wcatT);
    cudaGetSymbolAddress((void**)&bcat,  g_bcat);

    cudaFuncSetAttribute(gru_cluster_kernel,
                         cudaFuncAttributeMaxDynamicSharedMemorySize, GRU_SMEM_BYTES);

    prep_kernel<<<737, 256>>>(Wih, Wmz, Wmx, Wpz, Wcx, bmz, bmx, bpz, bcx);

    // x_proj = y @ W_ih^T + b_ih : [16384,768]
    gemm_kernel<64, 64, 32, 4, 4><<<dim3(12, 256), 256>>>(y, wihT, bih, xproj, 16384, 768, 128);

    // GRU recurrence -> enc [16384,256]
    gru_cluster_kernel<<<128, 384, GRU_SMEM_BYTES>>>(Whh, bhh, xproj, enc);

    // all heads fused: [16384,96] = enc @ Wcat^T + bcat
    gemm_kernel<64, 96, 32, 4, 6><<<dim3(1, 256), 256>>>(enc, wcatT, bcat, op, 16384, 96, 256);

    heads_out_kernel<<<2560, 512>>>(op, out);
    chol_kernel<<<16384, 512>>>(op, out);
}